// round 1
// baseline (speedup 1.0000x reference)
#include <cuda_runtime.h>
#include <math.h>

#define BATCH   2048
#define NGENES  4096
#define MAXCH   5120
#define OUTCOLS 341

// ping-pong activation / pre-activation buffers (42 MB each)
__device__ float g_bufA[BATCH * MAXCH];
__device__ float g_bufB[BATCH * MAXCH];
__device__ float g_mu[MAXCH];
__device__ float g_rstd[MAXCH];

__device__ __forceinline__ float* bufptr(int sel) { return sel == 0 ? g_bufA : g_bufB; }

// ---------------------------------------------------------------------------
// Small-term GEMM (s4: I=16,O=20 ; s3: I=144,O=20).
// Block = 256 threads handles 64 batch rows of one term.
// Input row t is concat( actPrev[b, t*split : t*split+split], x[b, t*Gs : +Gs] ).
// ---------------------------------------------------------------------------
__global__ void __launch_bounds__(256) gemm_tiny_kernel(
    int aSel, int chPrev, const float* __restrict__ x,
    const float* __restrict__ W, const float* __restrict__ bias, int hSel,
    int T, int I, int O, int Gs, int split, int CH)
{
    __shared__ float sA[64 * 144];
    __shared__ float sW[144 * 20];
    __shared__ float sb[20];

    const float* actPrev = (aSel >= 0) ? bufptr(aSel) : nullptr;
    float* h = bufptr(hSel);

    int t  = blockIdx.y;
    int b0 = blockIdx.x * 64;
    const float* Wt = W + (size_t)t * I * O;

    for (int idx = threadIdx.x; idx < I * O; idx += 256) sW[idx] = Wt[idx];
    for (int idx = threadIdx.x; idx < O; idx += 256)     sb[idx] = bias[t * O + idx];
    for (int idx = threadIdx.x; idx < 64 * I; idx += 256) {
        int r = idx / I, i = idx % I;
        int b = b0 + r;
        float v;
        if (i < split) v = actPrev[(size_t)b * chPrev + t * split + i];
        else           v = x[(size_t)b * NGENES + t * Gs + (i - split)];
        sA[r * I + i] = v;
    }
    __syncthreads();

    for (int out = threadIdx.x; out < 64 * O; out += 256) {
        int r = out / O, o = out % O;
        float acc = sb[o];
        const float* a = &sA[r * I];
        for (int k = 0; k < I; k++) acc = fmaf(a[k], sW[k * O + o], acc);
        h[(size_t)(b0 + r) * CH + t * O + o] = acc;
    }
}

// ---------------------------------------------------------------------------
// Big GEMM (s2, s1, s0). Tiles: BM=128, BN=64, BK=16; 256 threads, 8x4/thread.
// sA stored transposed [k][m] with stride 130 (conflict-free stores/loads).
// ---------------------------------------------------------------------------
__global__ void __launch_bounds__(256) gemm_big_kernel(
    int aSel, int chPrev, const float* __restrict__ x,
    const float* __restrict__ W, const float* __restrict__ bias, int hSel,
    int T, int I, int O, int Gs, int split, int CH)
{
    __shared__ float sA[16 * 130];
    __shared__ float sB[16 * 64];
    __shared__ float sBias[64];

    const float* actPrev = (aSel >= 0) ? bufptr(aSel) : nullptr;
    float* h = bufptr(hSel);

    int t  = blockIdx.z;
    int b0 = blockIdx.y * 128;
    int n0 = blockIdx.x * 64;
    int tx = threadIdx.x & 15;   // 16 n-groups (n = tx + j*16)
    int ty = threadIdx.x >> 4;   // 16 m-groups (m = ty*8 + i)
    const float* Wt = W + (size_t)t * I * O;

    if (threadIdx.x < 64) {
        int n = n0 + threadIdx.x;
        sBias[threadIdx.x] = (n < O) ? bias[t * O + n] : 0.f;
    }

    float acc[8][4];
#pragma unroll
    for (int i = 0; i < 8; i++)
#pragma unroll
        for (int j = 0; j < 4; j++) acc[i][j] = 0.f;

    for (int k0 = 0; k0 < I; k0 += 16) {
        __syncthreads();
        // A tile: 128 rows x 16 k, 8 elems/thread, coalesced along k
#pragma unroll
        for (int l = 0; l < 8; l++) {
            int idx = threadIdx.x + l * 256;
            int r = idx >> 4, kk = idx & 15;
            int k = k0 + kk;
            int b = b0 + r;
            float v = 0.f;
            if (k < I) {
                if (k < split) v = actPrev[(size_t)b * chPrev + t * split + k];
                else           v = x[(size_t)b * NGENES + t * Gs + (k - split)];
            }
            sA[kk * 130 + r] = v;
        }
        // B tile: 16 k x 64 n
#pragma unroll
        for (int l = 0; l < 4; l++) {
            int idx = threadIdx.x + l * 256;
            int kk = idx >> 6, n = idx & 63;
            int k = k0 + kk;
            float v = 0.f;
            if (k < I && n0 + n < O) v = Wt[(size_t)k * O + n0 + n];
            sB[kk * 64 + n] = v;
        }
        __syncthreads();
#pragma unroll
        for (int k = 0; k < 16; k++) {
            float a[8], bv[4];
#pragma unroll
            for (int i = 0; i < 8; i++) a[i] = sA[k * 130 + ty * 8 + i];
#pragma unroll
            for (int j = 0; j < 4; j++) bv[j] = sB[k * 64 + tx + j * 16];
#pragma unroll
            for (int i = 0; i < 8; i++)
#pragma unroll
                for (int j = 0; j < 4; j++) acc[i][j] = fmaf(a[i], bv[j], acc[i][j]);
        }
    }

#pragma unroll
    for (int i = 0; i < 8; i++) {
        int b = b0 + ty * 8 + i;
#pragma unroll
        for (int j = 0; j < 4; j++) {
            int n = n0 + tx + j * 16;
            if (n < O)
                h[(size_t)b * CH + t * O + n] = acc[i][j] + sBias[tx + j * 16];
        }
    }
}

// ---------------------------------------------------------------------------
// Column mean / rstd over the batch (deterministic, no atomics).
// grid.x = ceil(CH/64); block = 256 = 64 channels x 4 batch-lanes.
// ---------------------------------------------------------------------------
__global__ void __launch_bounds__(256) stats_kernel(int hSel, int CH)
{
    const float* h = bufptr(hSel);
    int c  = threadIdx.x & 63;
    int rb = threadIdx.x >> 6;
    int ch = blockIdx.x * 64 + c;
    float s = 0.f, q = 0.f;
    if (ch < CH) {
        for (int b = rb; b < BATCH; b += 4) {
            float v = h[(size_t)b * CH + ch];
            s += v; q += v * v;
        }
    }
    __shared__ float ss[256], sq[256];
    ss[threadIdx.x] = s; sq[threadIdx.x] = q;
    __syncthreads();
    if (rb == 0 && ch < CH) {
        float S = ss[c] + ss[c + 64] + ss[c + 128] + ss[c + 192];
        float Q = sq[c] + sq[c + 64] + sq[c + 128] + sq[c + 192];
        float mu  = S * (1.0f / BATCH);
        float var = Q * (1.0f / BATCH) - mu * mu;
        g_mu[ch]   = mu;
        g_rstd[ch] = rsqrtf(var + 1e-5f);
    }
}

// ---------------------------------------------------------------------------
// In-place normalize + tanh + per-term head. One warp per (b, t) row.
// grid.x = B*T/8, block = 256 (8 warps).
// ---------------------------------------------------------------------------
__global__ void __launch_bounds__(256) norm_head_kernel(
    int hSel,
    const float* __restrict__ gam, const float* __restrict__ bet,
    const float* __restrict__ hw, const float* __restrict__ hb,
    float* __restrict__ out, int T, int O, int CH, int colOff)
{
    float* h = bufptr(hSel);
    int w    = (blockIdx.x * blockDim.x + threadIdx.x) >> 5;
    int lane = threadIdx.x & 31;
    int b = w / T;
    int t = w % T;

    float dot = 0.f;
    for (int o = lane; o < O; o += 32) {
        int ch = t * O + o;
        float v = h[(size_t)b * CH + ch];
        float a = tanhf((v - g_mu[ch]) * g_rstd[ch] * gam[ch] + bet[ch]);
        h[(size_t)b * CH + ch] = a;
        dot += a * hw[ch];
    }
#pragma unroll
    for (int off = 16; off; off >>= 1) dot += __shfl_down_sync(0xffffffffu, dot, off);
    if (lane == 0)
        out[(size_t)b * OUTCOLS + colOff + t] = dot + hb[t];
}

// ---------------------------------------------------------------------------
// Host launch: 5 strata x (gemm -> stats -> norm/head), graph-capturable.
// ---------------------------------------------------------------------------
extern "C" void kernel_launch(void* const* d_in, const int* in_sizes, int n_in,
                              void* d_out, int out_size)
{
    const float* x = (const float*)d_in[0];
    float* out = (float*)d_out;

    // processing order leaves->root: s = 4,3,2,1,0
    struct St { int T, I, O, Gs, split, CH, chPrev, colOff; };
    const St S[5] = {
        {256,   16,   20,   16,    0, 5120,    0,   0},
        { 64,  144,   20,   64,   80, 1280, 5120, 256},
        { 16,  336,   77,  256,   80, 1232, 1280, 320},
        {  4, 1332,  308, 1024,  308, 1232, 1232, 336},
        {  1, 5328, 1229, 4096, 1232, 1229, 1232, 340},
    };

    int hSel = 0, aSel = -1;
    for (int j = 0; j < 5; j++) {
        const St& s = S[j];
        const float* W  = (const float*)d_in[1 + j * 6 + 0];
        const float* bi = (const float*)d_in[1 + j * 6 + 1];
        const float* ga = (const float*)d_in[1 + j * 6 + 2];
        const float* be = (const float*)d_in[1 + j * 6 + 3];
        const float* hw = (const float*)d_in[1 + j * 6 + 4];
        const float* hb = (const float*)d_in[1 + j * 6 + 5];

        if (j < 2) {
            dim3 grid(BATCH / 64, s.T);
            gemm_tiny_kernel<<<grid, 256>>>(aSel, s.chPrev, x, W, bi, hSel,
                                            s.T, s.I, s.O, s.Gs, s.split, s.CH);
        } else {
            dim3 grid((s.O + 63) / 64, BATCH / 128, s.T);
            gemm_big_kernel<<<grid, 256>>>(aSel, s.chPrev, x, W, bi, hSel,
                                           s.T, s.I, s.O, s.Gs, s.split, s.CH);
        }

        stats_kernel<<<(s.CH + 63) / 64, 256>>>(hSel, s.CH);

        norm_head_kernel<<<(BATCH * s.T) / 8, 256>>>(hSel, ga, be, hw, hb, out,
                                                     s.T, s.O, s.CH, s.colOff);

        aSel = hSel;
        hSel ^= 1;
    }
}

// round 3
// speedup vs baseline: 2.5202x; 2.5202x over previous
#include <cuda_runtime.h>
#include <cuda_bf16.h>
#include <math.h>
#include <stdint.h>

#define BATCH   2048
#define NGENES  4096
#define MAXCH   5120
#define OUTCOLS 341

// ---------------------------------------------------------------------------
// Static device buffers (no allocations allowed)
// ---------------------------------------------------------------------------
__device__ float g_bufA[BATCH * MAXCH];
__device__ float g_bufB[BATCH * MAXCH];
__device__ float g_mu[MAXCH];
__device__ float g_rstd[MAXCH];
__device__ float g_psum[16 * MAXCH];
__device__ float g_psqr[16 * MAXCH];
// bf16 hi/lo staging for tensor-core path
__device__ __nv_bfloat16 g_Ahi[12582912];   // max B*T*Ipad (s2: 2048*16*384)
__device__ __nv_bfloat16 g_Alo[12582912];
__device__ __nv_bfloat16 g_Whi[6607104];    // max T*O*Ipad (s0: 1229*5376)
__device__ __nv_bfloat16 g_Wlo[6607104];

__device__ __forceinline__ float* bufptr(int sel) { return sel == 0 ? g_bufA : g_bufB; }

__device__ __forceinline__ uint32_t smem_u32(const void* p) {
    uint32_t a;
    asm("{ .reg .u64 t; cvta.to.shared.u64 t, %1; cvt.u32.u64 %0, t; }" : "=r"(a) : "l"(p));
    return a;
}

#define CP_ASYNC16(dst, src, sz) \
    asm volatile("cp.async.cg.shared.global [%0], [%1], 16, %2;" \
                 :: "r"(dst), "l"(src), "r"(sz))
#define CP_COMMIT()  asm volatile("cp.async.commit_group;" ::: "memory")
#define CP_WAIT(N)   asm volatile("cp.async.wait_group %0;" :: "n"(N) : "memory")

__device__ __forceinline__ void ldsm4(uint32_t& r0, uint32_t& r1, uint32_t& r2,
                                      uint32_t& r3, uint32_t addr) {
    asm volatile("ldmatrix.sync.aligned.m8n8.x4.shared.b16 {%0,%1,%2,%3}, [%4];"
                 : "=r"(r0), "=r"(r1), "=r"(r2), "=r"(r3) : "r"(addr));
}
__device__ __forceinline__ void mma16816(float* d, uint32_t a0, uint32_t a1,
                                         uint32_t a2, uint32_t a3,
                                         uint32_t b0, uint32_t b1) {
    asm volatile("mma.sync.aligned.m16n8k16.row.col.f32.bf16.bf16.f32 "
                 "{%0,%1,%2,%3}, {%4,%5,%6,%7}, {%8,%9}, {%0,%1,%2,%3};"
                 : "+f"(d[0]), "+f"(d[1]), "+f"(d[2]), "+f"(d[3])
                 : "r"(a0), "r"(a1), "r"(a2), "r"(a3), "r"(b0), "r"(b1));
}

// ---------------------------------------------------------------------------
// Tiny-strata GEMM (s4: I=16, s3: I=144; O=20). 2 rows/thread, W in shared.
// ---------------------------------------------------------------------------
__global__ void __launch_bounds__(256) tiny_kernel(
    int aSel, int chPrev, const float* __restrict__ x,
    const float* __restrict__ W, const float* __restrict__ bias, int hSel,
    int I, int Gs, int split, int CH)
{
    __shared__ float sW[144 * 20];
    __shared__ float sb2[20];
    const float* act = (aSel >= 0) ? bufptr(aSel) : nullptr;
    float* h = bufptr(hSel);
    int t = blockIdx.y;
    const float* Wt = W + (size_t)t * I * 20;
    for (int i = threadIdx.x; i < I * 20; i += 256) sW[i] = Wt[i];
    if (threadIdx.x < 20) sb2[threadIdx.x] = bias[t * 20 + threadIdx.x];
    __syncthreads();

    int b0 = blockIdx.x * 512 + threadIdx.x;
    int b1 = b0 + 256;
    float a0c[20], a1c[20];
#pragma unroll
    for (int o = 0; o < 20; o++) { a0c[o] = sb2[o]; a1c[o] = sb2[o]; }

    const float* w = sW;
    if (split > 0) {
        const float* p0 = act + (size_t)b0 * chPrev + (size_t)t * split;
        const float* p1 = act + (size_t)b1 * chPrev + (size_t)t * split;
        for (int k = 0; k < split; k++) {
            float a0 = p0[k], a1 = p1[k];
#pragma unroll
            for (int o = 0; o < 20; o++) {
                float ww = w[o];
                a0c[o] = fmaf(a0, ww, a0c[o]);
                a1c[o] = fmaf(a1, ww, a1c[o]);
            }
            w += 20;
        }
    }
    {
        const float* q0 = x + (size_t)b0 * NGENES + (size_t)t * Gs;
        const float* q1 = x + (size_t)b1 * NGENES + (size_t)t * Gs;
        int I2 = I - split;
        for (int k = 0; k < I2; k++) {
            float a0 = q0[k], a1 = q1[k];
#pragma unroll
            for (int o = 0; o < 20; o++) {
                float ww = w[o];
                a0c[o] = fmaf(a0, ww, a0c[o]);
                a1c[o] = fmaf(a1, ww, a1c[o]);
            }
            w += 20;
        }
    }
    float* h0 = h + (size_t)b0 * CH + t * 20;
    float* h1 = h + (size_t)b1 * CH + t * 20;
#pragma unroll
    for (int o = 0; o < 20; o++) { h0[o] = a0c[o]; h1[o] = a1c[o]; }
}

// ---------------------------------------------------------------------------
// prepA: gather (children act ++ gene block), zero-pad K to Ipad, bf16 hi/lo.
// Layout [b][t][Ipad].
// ---------------------------------------------------------------------------
__global__ void __launch_bounds__(256) prepA_kernel(
    int aSel, int chPrev, const float* __restrict__ x,
    int T, int I, int Ipad, int Gs, int split)
{
    int idx = blockIdx.x * 256 + threadIdx.x;
    int TIp = T * Ipad;
    int b = idx / TIp;
    int rem = idx - b * TIp;
    int t = rem / Ipad;
    int i = rem - t * Ipad;
    const float* act = (aSel >= 0) ? bufptr(aSel) : nullptr;
    float v = 0.f;
    if (i < split)      v = act[(size_t)b * chPrev + t * split + i];
    else if (i < I)     v = x[(size_t)b * NGENES + t * Gs + (i - split)];
    __nv_bfloat16 hi = __float2bfloat16(v);
    float r = v - __bfloat162float(hi);
    g_Ahi[idx] = hi;
    g_Alo[idx] = __float2bfloat16(r);
}

// ---------------------------------------------------------------------------
// prepW: transpose W[t][i][o] -> Wt[t][o][i], pad i to Ipad, bf16 hi/lo.
// ---------------------------------------------------------------------------
__global__ void __launch_bounds__(256) prepW_kernel(
    const float* __restrict__ W, int I, int Ipad, int O)
{
    __shared__ float tile[32][33];
    int t = blockIdx.z;
    int i0 = blockIdx.x * 32, o0 = blockIdx.y * 32;
    int tx = threadIdx.x, ty = threadIdx.y;   // 32 x 8
    const float* Wt = W + (size_t)t * I * O;
#pragma unroll
    for (int j = 0; j < 4; j++) {
        int i = i0 + ty + j * 8, o = o0 + tx;
        tile[ty + j * 8][tx] = (i < I && o < O) ? Wt[(size_t)i * O + o] : 0.f;
    }
    __syncthreads();
#pragma unroll
    for (int j = 0; j < 4; j++) {
        int o = o0 + ty + j * 8, i = i0 + tx;
        if (o < O) {
            float v = tile[tx][ty + j * 8];
            __nv_bfloat16 hi = __float2bfloat16(v);
            size_t oi = ((size_t)t * O + o) * Ipad + i;
            g_Whi[oi] = hi;
            g_Wlo[oi] = __float2bfloat16(v - __bfloat162float(hi));
        }
    }
}

// ---------------------------------------------------------------------------
// Tensor-core GEMM via mma.sync (HMMA): h = A(bf16 hi/lo) @ W^T + bias.
// CTA 128x128, 8 warps (2x4), warp tile 64x32, K-chunk 32, cp.async 2-stage.
// SMEM row stride 80B (conflict-free ldmatrix).
// ---------------------------------------------------------------------------
#define ROWB     80
#define REG_SZ   10240            // 128 rows * 80 B
#define BUF_SZ   (4 * REG_SZ)     // Ahi, Alo, Bhi, Blo
#define SM_GEMM  (2 * BUF_SZ)     // 81920 B

__global__ void __launch_bounds__(256, 1) mma_gemm_kernel(
    const float* __restrict__ bias, int hSel, int T, int Ipad, int O, int CH)
{
    extern __shared__ char smem[];
    uint32_t sb = smem_u32(smem);
    float* h = bufptr(hSel);
    int tid = threadIdx.x, wid = tid >> 5, lane = tid & 31;
    int t = blockIdx.z, b0 = blockIdx.y * 128, n0 = blockIdx.x * 128;
    int m0w = (wid >> 2) * 64;         // warp row offset (0/64)
    int n0w = (wid & 3) * 32;          // warp col offset
    int nC = Ipad >> 5;                // K chunks of 32
    int Arow = T * Ipad;

    float acc[4][4][4];
#pragma unroll
    for (int a = 0; a < 4; a++)
#pragma unroll
        for (int b = 0; b < 4; b++)
#pragma unroll
            for (int c = 0; c < 4; c++) acc[a][b][c] = 0.f;

    // per-thread load coords: 512 16B-chunks per 128x32 region, 2 per thread
    int r0 = (tid + 0) >> 2,   c0 = (tid + 0) & 3;
    int r1 = (tid + 256) >> 2, c1 = (tid + 256) & 3;
    int bn0ok = (n0 + r0 < O) ? 16 : 0;
    int bn1ok = (n0 + r1 < O) ? 16 : 0;
    size_t aOff0 = (size_t)(b0 + r0) * Arow + (size_t)t * Ipad + c0 * 8;
    size_t aOff1 = (size_t)(b0 + r1) * Arow + (size_t)t * Ipad + c1 * 8;
    size_t bOff0 = ((size_t)t * O + min(n0 + r0, O - 1)) * Ipad + c0 * 8;
    size_t bOff1 = ((size_t)t * O + min(n0 + r1, O - 1)) * Ipad + c1 * 8;
    uint32_t d0 = r0 * ROWB + c0 * 16;
    uint32_t d1 = r1 * ROWB + c1 * 16;

#define LOAD_CHUNK(cIdx) do {                                                  \
        uint32_t base = sb + ((cIdx) & 1) * BUF_SZ;                            \
        int k0 = (cIdx) << 5;                                                  \
        CP_ASYNC16(base + d0,              g_Ahi + aOff0 + k0, 16);            \
        CP_ASYNC16(base + d1,              g_Ahi + aOff1 + k0, 16);            \
        CP_ASYNC16(base + REG_SZ + d0,     g_Alo + aOff0 + k0, 16);            \
        CP_ASYNC16(base + REG_SZ + d1,     g_Alo + aOff1 + k0, 16);            \
        CP_ASYNC16(base + 2 * REG_SZ + d0, g_Whi + bOff0 + k0, bn0ok);         \
        CP_ASYNC16(base + 2 * REG_SZ + d1, g_Whi + bOff1 + k0, bn1ok);         \
        CP_ASYNC16(base + 3 * REG_SZ + d0, g_Wlo + bOff0 + k0, bn0ok);         \
        CP_ASYNC16(base + 3 * REG_SZ + d1, g_Wlo + bOff1 + k0, bn1ok);         \
        CP_COMMIT();                                                           \
    } while (0)

    // ldmatrix lane addressing
    uint32_t aRowSel = (lane & 15);
    uint32_t aKHalf  = (lane >> 4) * 16;          // bytes
    uint32_t bRowSel = (lane & 7) + ((lane >> 4) << 3);
    uint32_t bKHalf  = ((lane >> 3) & 1) * 16;    // bytes

    LOAD_CHUNK(0);

    for (int c = 0; c < nC; c++) {
        if (c + 1 < nC) { LOAD_CHUNK(c + 1); CP_WAIT(1); }
        else            { CP_WAIT(0); }
        __syncthreads();

        uint32_t base = sb + (c & 1) * BUF_SZ;
        uint32_t aHi = base;
        uint32_t aLo = base + REG_SZ;
        uint32_t bHi = base + 2 * REG_SZ;
        uint32_t bLo = base + 3 * REG_SZ;

#pragma unroll
        for (int ks = 0; ks < 2; ks++) {
            uint32_t kOffA = ks * 32 + aKHalf;
            uint32_t kOffB = ks * 32 + bKHalf;
            uint32_t ah[4][4], al[4][4], bh[4][2], bl[4][2];
#pragma unroll
            for (int mt = 0; mt < 4; mt++) {
                uint32_t ra = (m0w + mt * 16 + aRowSel) * ROWB + kOffA;
                ldsm4(ah[mt][0], ah[mt][1], ah[mt][2], ah[mt][3], aHi + ra);
                ldsm4(al[mt][0], al[mt][1], al[mt][2], al[mt][3], aLo + ra);
            }
#pragma unroll
            for (int np = 0; np < 2; np++) {
                uint32_t rb = (n0w + np * 16 + bRowSel) * ROWB + kOffB;
                uint32_t q0, q1, q2, q3;
                ldsm4(q0, q1, q2, q3, bHi + rb);
                bh[np * 2][0] = q0; bh[np * 2][1] = q1;
                bh[np * 2 + 1][0] = q2; bh[np * 2 + 1][1] = q3;
                ldsm4(q0, q1, q2, q3, bLo + rb);
                bl[np * 2][0] = q0; bl[np * 2][1] = q1;
                bl[np * 2 + 1][0] = q2; bl[np * 2 + 1][1] = q3;
            }
#pragma unroll
            for (int mt = 0; mt < 4; mt++)
#pragma unroll
                for (int nt = 0; nt < 4; nt++) {
                    mma16816(acc[mt][nt], ah[mt][0], ah[mt][1], ah[mt][2], ah[mt][3],
                             bh[nt][0], bh[nt][1]);
                    mma16816(acc[mt][nt], ah[mt][0], ah[mt][1], ah[mt][2], ah[mt][3],
                             bl[nt][0], bl[nt][1]);
                    mma16816(acc[mt][nt], al[mt][0], al[mt][1], al[mt][2], al[mt][3],
                             bh[nt][0], bh[nt][1]);
                }
        }
        __syncthreads();
    }

    // epilogue: write h += bias
    const float* bt = bias + (size_t)t * O;
#pragma unroll
    for (int mt = 0; mt < 4; mt++) {
        int mRow = b0 + m0w + mt * 16 + (lane >> 2);
        float* h0 = h + (size_t)mRow * CH + (size_t)t * O;
        float* h1 = h0 + 8 * CH;
#pragma unroll
        for (int nt = 0; nt < 4; nt++) {
            int n = n0 + n0w + nt * 8 + (lane & 3) * 2;
            if (n < O) {
                h0[n] = acc[mt][nt][0] + __ldg(bt + n);
                h1[n] = acc[mt][nt][2] + __ldg(bt + n);
            }
            if (n + 1 < O) {
                h0[n + 1] = acc[mt][nt][1] + __ldg(bt + n + 1);
                h1[n + 1] = acc[mt][nt][3] + __ldg(bt + n + 1);
            }
        }
    }
}

// ---------------------------------------------------------------------------
// Batch stats, 2-pass deterministic tree
// ---------------------------------------------------------------------------
__global__ void __launch_bounds__(256) stats1_kernel(int hSel, int CH)
{
    const float* h = bufptr(hSel);
    int c  = threadIdx.x & 63;
    int rb = threadIdx.x >> 6;
    int ch = blockIdx.x * 64 + c;
    int r0 = blockIdx.y * 128;
    float s = 0.f, q = 0.f;
    if (ch < CH) {
        for (int b = r0 + rb; b < r0 + 128; b += 4) {
            float v = h[(size_t)b * CH + ch];
            s += v; q += v * v;
        }
    }
    __shared__ float ss[256], sq[256];
    ss[threadIdx.x] = s; sq[threadIdx.x] = q;
    __syncthreads();
    if (rb == 0 && ch < CH) {
        g_psum[blockIdx.y * MAXCH + ch] = ss[c] + ss[c + 64] + ss[c + 128] + ss[c + 192];
        g_psqr[blockIdx.y * MAXCH + ch] = sq[c] + sq[c + 64] + sq[c + 128] + sq[c + 192];
    }
}

__global__ void __launch_bounds__(256) stats2_kernel(int CH)
{
    int ch = blockIdx.x * 256 + threadIdx.x;
    if (ch >= CH) return;
    float S = 0.f, Q = 0.f;
#pragma unroll
    for (int p = 0; p < 16; p++) { S += g_psum[p * MAXCH + ch]; Q += g_psqr[p * MAXCH + ch]; }
    float mu  = S * (1.0f / BATCH);
    float var = Q * (1.0f / BATCH) - mu * mu;
    g_mu[ch]   = mu;
    g_rstd[ch] = rsqrtf(var + 1e-5f);
}

// ---------------------------------------------------------------------------
// Normalize + tanh (in place) + per-term scalar head. One warp per (b, t).
// ---------------------------------------------------------------------------
__global__ void __launch_bounds__(256) norm_head_kernel(
    int hSel,
    const float* __restrict__ gam, const float* __restrict__ bet,
    const float* __restrict__ hw, const float* __restrict__ hb,
    float* __restrict__ out, int T, int O, int CH, int colOff)
{
    float* h = bufptr(hSel);
    int w    = (blockIdx.x * blockDim.x + threadIdx.x) >> 5;
    int lane = threadIdx.x & 31;
    int b = w / T;
    int t = w - b * T;

    float dot = 0.f;
    for (int o = lane; o < O; o += 32) {
        int ch = t * O + o;
        float v = h[(size_t)b * CH + ch];
        float a = tanhf((v - g_mu[ch]) * g_rstd[ch] * gam[ch] + bet[ch]);
        h[(size_t)b * CH + ch] = a;
        dot += a * hw[ch];
    }
#pragma unroll
    for (int off = 16; off; off >>= 1) dot += __shfl_down_sync(0xffffffffu, dot, off);
    if (lane == 0)
        out[(size_t)b * OUTCOLS + colOff + t] = dot + hb[t];
}

// ---------------------------------------------------------------------------
// Host: 5 strata. s4,s3 -> tiny SIMT; s2,s1,s0 -> prep + HMMA GEMM.
// ---------------------------------------------------------------------------
extern "C" void kernel_launch(void* const* d_in, const int* in_sizes, int n_in,
                              void* d_out, int out_size)
{
    const float* x = (const float*)d_in[0];
    float* out = (float*)d_out;

    cudaFuncSetAttribute(mma_gemm_kernel,
                         cudaFuncAttributeMaxDynamicSharedMemorySize, SM_GEMM);

    struct St { int T, I, Ipad, O, Gs, split, CH, colOff; };
    const St S[5] = {
        {256,   16,   64,   20,   16,    0, 5120,   0},
        { 64,  144,  192,   20,   64,   80, 1280, 256},
        { 16,  336,  384,   77,  256,   80, 1232, 320},
        {  4, 1332, 1344,  308, 1024,  308, 1232, 336},
        {  1, 5328, 5376, 1229, 4096, 1232, 1229, 340},
    };

    int hSel = 0, aSel = -1;
    for (int j = 0; j < 5; j++) {
        const St& s = S[j];
        const float* W  = (const float*)d_in[1 + j * 6 + 0];
        const float* bi = (const float*)d_in[1 + j * 6 + 1];
        const float* ga = (const float*)d_in[1 + j * 6 + 2];
        const float* be = (const float*)d_in[1 + j * 6 + 3];
        const float* hw = (const float*)d_in[1 + j * 6 + 4];
        const float* hb = (const float*)d_in[1 + j * 6 + 5];
        int chPrev = (j > 0) ? S[j - 1].CH : 0;

        if (j < 2) {
            dim3 grid(BATCH / 512, s.T);
            tiny_kernel<<<grid, 256>>>(aSel, chPrev, x, W, bi, hSel,
                                       s.I, s.Gs, s.split, s.CH);
        } else {
            int total = BATCH * s.T * s.Ipad;
            prepA_kernel<<<total / 256, 256>>>(aSel, chPrev, x, s.T, s.I, s.Ipad,
                                               s.Gs, s.split);
            dim3 wg(s.Ipad / 32, (s.O + 31) / 32, s.T);
            prepW_kernel<<<wg, dim3(32, 8)>>>(W, s.I, s.Ipad, s.O);
            dim3 gg((s.O + 127) / 128, BATCH / 128, s.T);
            mma_gemm_kernel<<<gg, 256, SM_GEMM>>>(bi, hSel, s.T, s.Ipad, s.O, s.CH);
        }

        stats1_kernel<<<dim3((s.CH + 63) / 64, 16), 256>>>(hSel, s.CH);
        stats2_kernel<<<(s.CH + 255) / 256, 256>>>(s.CH);
        norm_head_kernel<<<(BATCH * s.T) / 8, 256>>>(hSel, ga, be, hw, hb, out,
                                                     s.T, s.O, s.CH, s.colOff);
        aSel = hSel;
        hSel ^= 1;
    }
}